// round 1
// baseline (speedup 1.0000x reference)
#include <cuda_runtime.h>

#define NN 10000
#define EE 640000
#define CC 128     // in_channels
#define HH 512     // hidden
#define OO 128     // out

// ---- static scratch (no allocations allowed) ----
__device__ int   g_count[NN];
__device__ int   g_offset[NN];
__device__ int   g_cursor[NN];
__device__ int   g_coledge[EE];
__device__ float g_hcat[NN * 2 * CC];   // [N, 256] = concat(x, mean)
__device__ float g_hmid[NN * HH];       // [N, 512]

// ---------------- CSR build ----------------
__global__ void k_zero() {
    int i = blockIdx.x * blockDim.x + threadIdx.x;
    if (i < NN) { g_count[i] = 0; g_cursor[i] = 0; }
}

__global__ void k_count(const int* __restrict__ ei) {
    int e = blockIdx.x * blockDim.x + threadIdx.x;
    if (e < EE) atomicAdd(&g_count[ei[e]], 1);
}

// single-block exclusive scan over g_count (N=10000, chunk=10 per thread)
__global__ void k_scan() {
    __shared__ int s[1024];
    const int CH = 10;
    int t = threadIdx.x;
    int base = t * CH;
    int vals[CH];
    int local = 0;
    #pragma unroll
    for (int i = 0; i < CH; i++) {
        int idx = base + i;
        int v = (idx < NN) ? g_count[idx] : 0;
        vals[i] = v;
        local += v;
    }
    s[t] = local;
    __syncthreads();
    // Hillis-Steele inclusive scan over 1024 partials
    for (int d = 1; d < 1024; d <<= 1) {
        int v = (t >= d) ? s[t - d] : 0;
        __syncthreads();
        s[t] += v;
        __syncthreads();
    }
    int excl = s[t] - local;
    #pragma unroll
    for (int i = 0; i < CH; i++) {
        int idx = base + i;
        if (idx < NN) { g_offset[idx] = excl; excl += vals[i]; }
    }
}

__global__ void k_fill(const int* __restrict__ ei) {
    int e = blockIdx.x * blockDim.x + threadIdx.x;
    if (e < EE) {
        int r = ei[e];
        int c = ei[EE + e];
        int pos = g_offset[r] + atomicAdd(&g_cursor[r], 1);
        g_coledge[pos] = c;
    }
}

// ---------------- aggregation: one warp per destination row ----------------
__global__ void k_agg(const float* __restrict__ x) {
    int gw   = (blockIdx.x * blockDim.x + threadIdx.x) >> 5;
    int lane = threadIdx.x & 31;
    if (gw >= NN) return;
    const float4* x4 = reinterpret_cast<const float4*>(x);

    float4 xv = x4[gw * 32 + lane];

    float ax = 0.f, ay = 0.f, az = 0.f, aw = 0.f;
    int start = g_offset[gw];
    int cnt   = g_count[gw];
    int i = 0;
    for (; i + 4 <= cnt; i += 4) {
        int i0 = g_coledge[start + i + 0];
        int i1 = g_coledge[start + i + 1];
        int i2 = g_coledge[start + i + 2];
        int i3 = g_coledge[start + i + 3];
        float4 v0 = x4[i0 * 32 + lane];
        float4 v1 = x4[i1 * 32 + lane];
        float4 v2 = x4[i2 * 32 + lane];
        float4 v3 = x4[i3 * 32 + lane];
        ax += (v0.x + v1.x) + (v2.x + v3.x);
        ay += (v0.y + v1.y) + (v2.y + v3.y);
        az += (v0.z + v1.z) + (v2.z + v3.z);
        aw += (v0.w + v1.w) + (v2.w + v3.w);
    }
    for (; i < cnt; i++) {
        int id = g_coledge[start + i];
        float4 v = x4[id * 32 + lane];
        ax += v.x; ay += v.y; az += v.z; aw += v.w;
    }
    float inv = 1.0f / (float)max(cnt, 1);
    float4 m = make_float4(ax * inv, ay * inv, az * inv, aw * inv);

    float4* hc = reinterpret_cast<float4*>(g_hcat);
    hc[gw * 64 + lane]      = xv;  // first 128 cols: x
    hc[gw * 64 + 32 + lane] = m;   // next 128 cols: neighbor mean
}

// ---------------- tiled fp32 GEMM: C = relu?(A @ B + bias) ----------------
// A [M,K] row-major, B [K,Nn] row-major. BM=64, BN=64, BK=16, 256 threads, 4x4/thread.
template <bool RELU>
__global__ void __launch_bounds__(256) k_gemm(
    const float* __restrict__ A, const float* __restrict__ B,
    const float* __restrict__ bias, float* __restrict__ Cout,
    int M, int Nn, int K)
{
    __shared__ float As[16][64];   // [k][m]
    __shared__ float Bs[16][64];   // [k][n]

    int t  = threadIdx.x;
    int ty = t >> 4;       // 0..15
    int tx = t & 15;       // 0..15
    int bm = blockIdx.x * 64;
    int bn = blockIdx.y * 64;

    float acc[4][4] = {};

    int lrowA = t >> 2;    // 0..63
    int lc4A  = t & 3;     // 0..3  (float4 within 16-wide K)
    int browB = t >> 4;    // 0..15
    int bc4B  = t & 15;    // 0..15 (float4 within 64-wide N)

    for (int k0 = 0; k0 < K; k0 += 16) {
        // load A tile (transposed into As[k][m])
        int arow = bm + lrowA;
        float4 av = make_float4(0.f, 0.f, 0.f, 0.f);
        if (arow < M)
            av = *reinterpret_cast<const float4*>(&A[(size_t)arow * K + k0 + lc4A * 4]);
        As[lc4A * 4 + 0][lrowA] = av.x;
        As[lc4A * 4 + 1][lrowA] = av.y;
        As[lc4A * 4 + 2][lrowA] = av.z;
        As[lc4A * 4 + 3][lrowA] = av.w;

        // load B tile
        float4 bv = *reinterpret_cast<const float4*>(&B[(size_t)(k0 + browB) * Nn + bn + bc4B * 4]);
        *reinterpret_cast<float4*>(&Bs[browB][bc4B * 4]) = bv;

        __syncthreads();

        #pragma unroll
        for (int kk = 0; kk < 16; kk++) {
            float4 a = *reinterpret_cast<const float4*>(&As[kk][ty * 4]);
            float4 b = *reinterpret_cast<const float4*>(&Bs[kk][tx * 4]);
            float ar[4] = {a.x, a.y, a.z, a.w};
            float br[4] = {b.x, b.y, b.z, b.w};
            #pragma unroll
            for (int i = 0; i < 4; i++)
                #pragma unroll
                for (int j = 0; j < 4; j++)
                    acc[i][j] = fmaf(ar[i], br[j], acc[i][j]);
        }
        __syncthreads();
    }

    #pragma unroll
    for (int i = 0; i < 4; i++) {
        int row = bm + ty * 4 + i;
        if (row >= M) continue;
        #pragma unroll
        for (int j = 0; j < 4; j++) {
            int col = bn + tx * 4 + j;
            float v = acc[i][j] + bias[col];
            if (RELU) v = fmaxf(v, 0.f);
            Cout[(size_t)row * Nn + col] = v;
        }
    }
}

extern "C" void kernel_launch(void* const* d_in, const int* in_sizes, int n_in,
                              void* d_out, int out_size)
{
    const float* x  = (const float*)d_in[0];
    const int*   ei = (const int*)d_in[1];    // [2,E] int32 (row then col)
    const float* w1 = (const float*)d_in[2];  // [256,512]
    const float* b1 = (const float*)d_in[3];  // [512]
    const float* w2 = (const float*)d_in[4];  // [512,128]
    const float* b2 = (const float*)d_in[5];  // [128]
    float* out = (float*)d_out;               // [N,128]

    float* hcat; float* hmid;
    cudaGetSymbolAddress((void**)&hcat, g_hcat);
    cudaGetSymbolAddress((void**)&hmid, g_hmid);

    k_zero<<<(NN + 255) / 256, 256>>>();
    k_count<<<(EE + 255) / 256, 256>>>(ei);
    k_scan<<<1, 1024>>>();
    k_fill<<<(EE + 255) / 256, 256>>>(ei);
    k_agg<<<(NN * 32 + 255) / 256, 256>>>(x);

    dim3 g1((NN + 63) / 64, HH / 64);   // 157 x 8
    k_gemm<true><<<g1, 256>>>(hcat, w1, b1, hmid, NN, HH, 2 * CC);

    dim3 g2((NN + 63) / 64, OO / 64);   // 157 x 2
    k_gemm<false><<<g2, 256>>>(hmid, w2, b2, out, NN, OO, HH);
}

// round 2
// speedup vs baseline: 1.0529x; 1.0529x over previous
#include <cuda_runtime.h>

#define NN 10000
#define EE 640000
#define CC 128     // in_channels
#define HH 512     // hidden
#define OO 128     // out

// ---- static scratch (no allocations allowed) ----
__device__ int   g_count[NN];
__device__ int   g_offset[NN];
__device__ int   g_cursor[NN];
__device__ int   g_coledge[EE];
__device__ __align__(16) float g_hcat[NN * 2 * CC];   // [N, 256]
__device__ __align__(16) float g_hmid[NN * HH];       // [N, 512]

// ---------------- CSR build ----------------
__global__ void k_zero() {
    int i = blockIdx.x * blockDim.x + threadIdx.x;
    if (i < NN) { g_count[i] = 0; g_cursor[i] = 0; }
}

__global__ void k_count(const int* __restrict__ ei) {
    int e = blockIdx.x * blockDim.x + threadIdx.x;
    if (e < EE) atomicAdd(&g_count[ei[e]], 1);
}

// single-block exclusive scan over g_count (N=10000, chunk=10 per thread)
__global__ void k_scan() {
    __shared__ int s[1024];
    const int CH = 10;
    int t = threadIdx.x;
    int base = t * CH;
    int vals[CH];
    int local = 0;
    #pragma unroll
    for (int i = 0; i < CH; i++) {
        int idx = base + i;
        int v = (idx < NN) ? g_count[idx] : 0;
        vals[i] = v;
        local += v;
    }
    s[t] = local;
    __syncthreads();
    for (int d = 1; d < 1024; d <<= 1) {
        int v = (t >= d) ? s[t - d] : 0;
        __syncthreads();
        s[t] += v;
        __syncthreads();
    }
    int excl = s[t] - local;
    #pragma unroll
    for (int i = 0; i < CH; i++) {
        int idx = base + i;
        if (idx < NN) { g_offset[idx] = excl; excl += vals[i]; }
    }
}

__global__ void k_fill(const int* __restrict__ ei) {
    int e = blockIdx.x * blockDim.x + threadIdx.x;
    if (e < EE) {
        int r = ei[e];
        int c = ei[EE + e];
        int pos = g_offset[r] + atomicAdd(&g_cursor[r], 1);
        g_coledge[pos] = c;
    }
}

// ---------------- aggregation: one warp per destination row ----------------
__global__ void k_agg(const float* __restrict__ x) {
    int gw   = (blockIdx.x * blockDim.x + threadIdx.x) >> 5;
    int lane = threadIdx.x & 31;
    if (gw >= NN) return;
    const float4* x4 = reinterpret_cast<const float4*>(x);

    float4 xv = x4[gw * 32 + lane];

    float ax = 0.f, ay = 0.f, az = 0.f, aw = 0.f;
    int start = g_offset[gw];
    int cnt   = g_count[gw];
    int i = 0;
    for (; i + 4 <= cnt; i += 4) {
        int i0 = g_coledge[start + i + 0];
        int i1 = g_coledge[start + i + 1];
        int i2 = g_coledge[start + i + 2];
        int i3 = g_coledge[start + i + 3];
        float4 v0 = x4[i0 * 32 + lane];
        float4 v1 = x4[i1 * 32 + lane];
        float4 v2 = x4[i2 * 32 + lane];
        float4 v3 = x4[i3 * 32 + lane];
        ax += (v0.x + v1.x) + (v2.x + v3.x);
        ay += (v0.y + v1.y) + (v2.y + v3.y);
        az += (v0.z + v1.z) + (v2.z + v3.z);
        aw += (v0.w + v1.w) + (v2.w + v3.w);
    }
    for (; i < cnt; i++) {
        int id = g_coledge[start + i];
        float4 v = x4[id * 32 + lane];
        ax += v.x; ay += v.y; az += v.z; aw += v.w;
    }
    float inv = 1.0f / (float)max(cnt, 1);
    float4 m = make_float4(ax * inv, ay * inv, az * inv, aw * inv);

    float4* hc = reinterpret_cast<float4*>(g_hcat);
    hc[gw * 64 + lane]      = xv;
    hc[gw * 64 + 32 + lane] = m;
}

// ---------------- packed-f32x2 tiled GEMM ----------------
// C = relu?(A @ B + bias). A [M,K] rm, B [K,Nn] rm.
// BM=128, BN=64, BK=16, 256 threads, per-thread 8(M)x4(N),
// accumulators packed in pairs along M via fma.rn.f32x2.

__device__ __forceinline__ void ffma2(unsigned long long& d,
                                      unsigned long long a,
                                      unsigned long long b) {
    asm("fma.rn.f32x2 %0, %1, %2, %0;" : "+l"(d) : "l"(a), "l"(b));
}
__device__ __forceinline__ unsigned long long dup2(float v) {
    unsigned long long r;
    asm("mov.b64 %0, {%1, %1};" : "=l"(r) : "f"(v));
    return r;
}
__device__ __forceinline__ float lo32(unsigned long long v) {
    return __uint_as_float((unsigned)(v & 0xffffffffull));
}
__device__ __forceinline__ float hi32(unsigned long long v) {
    return __uint_as_float((unsigned)(v >> 32));
}

#define BMa 128
#define BNa 64
#define BKa 16
#define ASTRIDE (BMa + 4)   // 132 floats per k-row; 528B keeps 16B alignment

template <bool RELU>
__global__ void __launch_bounds__(256) k_gemm2x(
    const float* __restrict__ A, const float* __restrict__ B,
    const float* __restrict__ bias, float* __restrict__ Cout,
    int M, int Nn, int K)
{
    __shared__ __align__(16) float As[BKa * ASTRIDE];
    __shared__ __align__(16) float Bs[BKa * BNa];

    int t  = threadIdx.x;
    int tx = t & 15;       // 0..15 -> N
    int ty = t >> 4;       // 0..15 -> M (8 rows each)
    int bm = blockIdx.x * BMa;
    int bn = blockIdx.y * BNa;

    // acc[p][j]: packed pair (row 2p, row 2p+1) x col j, p=0..3, j=0..3
    unsigned long long acc[4][4];
    #pragma unroll
    for (int p = 0; p < 4; p++)
        #pragma unroll
        for (int j = 0; j < 4; j++) acc[p][j] = 0ull;

    int lrowA = t >> 2;    // 0..63 (and +64)
    int lc4A  = t & 3;     // float4 index within BK=16
    int browB = t >> 4;    // 0..15 k-row
    int bc4B  = t & 15;    // float4 index within BN=64

    for (int k0 = 0; k0 < K; k0 += BKa) {
        // A tile: transpose into As[k][m]
        #pragma unroll
        for (int rep = 0; rep < 2; rep++) {
            int lm = lrowA + rep * 64;
            int arow = bm + lm;
            float4 av = make_float4(0.f, 0.f, 0.f, 0.f);
            if (arow < M)
                av = *reinterpret_cast<const float4*>(&A[(size_t)arow * K + k0 + lc4A * 4]);
            As[(lc4A * 4 + 0) * ASTRIDE + lm] = av.x;
            As[(lc4A * 4 + 1) * ASTRIDE + lm] = av.y;
            As[(lc4A * 4 + 2) * ASTRIDE + lm] = av.z;
            As[(lc4A * 4 + 3) * ASTRIDE + lm] = av.w;
        }
        // B tile
        float4 bv = *reinterpret_cast<const float4*>(&B[(size_t)(k0 + browB) * Nn + bn + bc4B * 4]);
        *reinterpret_cast<float4*>(&Bs[browB * BNa + bc4B * 4]) = bv;

        __syncthreads();

        #pragma unroll
        for (int kk = 0; kk < BKa; kk++) {
            // 4 packed A pairs (rows ty*8 .. ty*8+7)
            const ulonglong2* ap =
                reinterpret_cast<const ulonglong2*>(&As[kk * ASTRIDE + ty * 8]);
            ulonglong2 a01 = ap[0];
            ulonglong2 a23 = ap[1];
            unsigned long long ar[4] = {a01.x, a01.y, a23.x, a23.y};

            float4 b4 = *reinterpret_cast<const float4*>(&Bs[kk * BNa + tx * 4]);
            unsigned long long bd[4] = {dup2(b4.x), dup2(b4.y), dup2(b4.z), dup2(b4.w)};

            #pragma unroll
            for (int p = 0; p < 4; p++)
                #pragma unroll
                for (int j = 0; j < 4; j++)
                    ffma2(acc[p][j], ar[p], bd[j]);
        }
        __syncthreads();
    }

    // epilogue
    float bvals[4];
    #pragma unroll
    for (int j = 0; j < 4; j++) bvals[j] = bias[bn + tx * 4 + j];

    #pragma unroll
    for (int p = 0; p < 4; p++) {
        int row0 = bm + ty * 8 + 2 * p;
        #pragma unroll
        for (int half = 0; half < 2; half++) {
            int row = row0 + half;
            if (row >= M) continue;
            float4 o;
            float v0 = (half ? hi32(acc[p][0]) : lo32(acc[p][0])) + bvals[0];
            float v1 = (half ? hi32(acc[p][1]) : lo32(acc[p][1])) + bvals[1];
            float v2 = (half ? hi32(acc[p][2]) : lo32(acc[p][2])) + bvals[2];
            float v3 = (half ? hi32(acc[p][3]) : lo32(acc[p][3])) + bvals[3];
            if (RELU) {
                v0 = fmaxf(v0, 0.f); v1 = fmaxf(v1, 0.f);
                v2 = fmaxf(v2, 0.f); v3 = fmaxf(v3, 0.f);
            }
            o = make_float4(v0, v1, v2, v3);
            *reinterpret_cast<float4*>(&Cout[(size_t)row * Nn + bn + tx * 4]) = o;
        }
    }
}

extern "C" void kernel_launch(void* const* d_in, const int* in_sizes, int n_in,
                              void* d_out, int out_size)
{
    const float* x  = (const float*)d_in[0];
    const int*   ei = (const int*)d_in[1];    // [2,E] int32
    const float* w1 = (const float*)d_in[2];  // [256,512]
    const float* b1 = (const float*)d_in[3];  // [512]
    const float* w2 = (const float*)d_in[4];  // [512,128]
    const float* b2 = (const float*)d_in[5];  // [128]
    float* out = (float*)d_out;               // [N,128]

    float* hcat; float* hmid;
    cudaGetSymbolAddress((void**)&hcat, g_hcat);
    cudaGetSymbolAddress((void**)&hmid, g_hmid);

    k_zero<<<(NN + 255) / 256, 256>>>();
    k_count<<<(EE + 255) / 256, 256>>>(ei);
    k_scan<<<1, 1024>>>();
    k_fill<<<(EE + 255) / 256, 256>>>(ei);
    k_agg<<<(NN * 32 + 255) / 256, 256>>>(x);

    dim3 g1((NN + BMa - 1) / BMa, HH / BNa);   // 79 x 8
    k_gemm2x<true><<<g1, 256>>>(hcat, w1, b1, hmid, NN, HH, 2 * CC);

    dim3 g2((NN + BMa - 1) / BMa, OO / BNa);   // 79 x 2
    k_gemm2x<false><<<g2, 256>>>(hmid, w2, b2, out, NN, OO, HH);
}